// round 2
// baseline (speedup 1.0000x reference)
#include <cuda_runtime.h>
#include <cuda_bf16.h>

// SpikeAmplifier: IF neuron with lateral amplification.
// input: (T=128, N=16, C=1, J=8192) f32 ; lateral_weight: (J=8192,) f32
// out:   (T, N, C, J) f32 spikes.
// Per neuron (n,j), sequential over t:
//   h = y_prev * (h + w[j]); v += x_t + h; s = (v >= 1); v *= (1 - s); emit s.

constexpr int T_STEPS = 128;
constexpr int N_BATCH = 16;
constexpr int J_DIM   = 8192;
constexpr int NCJ     = N_BATCH * J_DIM;     // 131072 neurons
constexpr int S4      = NCJ / 4;             // 32768 float4 per timestep
constexpr int J4      = J_DIM / 4;           // 2048 float4 in weight
constexpr int CH      = 8;                   // prefetch depth (timesteps)

__global__ __launch_bounds__(128, 8)
void spike_amplifier_kernel(const float4* __restrict__ in,
                            const float4* __restrict__ w4,
                            float4* __restrict__ out) {
    const int idx = blockIdx.x * blockDim.x + threadIdx.x;   // 0 .. S4-1
    const int j4  = idx & (J4 - 1);                          // weight group
    const float4 wv = w4[j4];

    float h0 = 0.f, h1 = 0.f, h2 = 0.f, h3 = 0.f;
    float v0 = 0.f, v1 = 0.f, v2 = 0.f, v3 = 0.f;
    float y0 = 0.f, y1 = 0.f, y2 = 0.f, y3 = 0.f;

    #pragma unroll 1
    for (int tc = 0; tc < T_STEPS; tc += CH) {
        // Batch of CH independent loads -> MLP, hides DRAM latency.
        float4 buf[CH];
        #pragma unroll
        for (int c = 0; c < CH; c++) {
            buf[c] = in[(size_t)(tc + c) * S4 + idx];
        }

        #pragma unroll
        for (int c = 0; c < CH; c++) {
            // h = y_prev * (h + w)
            h0 = y0 * (h0 + wv.x);
            h1 = y1 * (h1 + wv.y);
            h2 = y2 * (h2 + wv.z);
            h3 = y3 * (h3 + wv.w);
            // v += x + h
            v0 += buf[c].x + h0;
            v1 += buf[c].y + h1;
            v2 += buf[c].z + h2;
            v3 += buf[c].w + h3;
            // spike + hard reset
            y0 = (v0 >= 1.0f) ? 1.0f : 0.0f;
            y1 = (v1 >= 1.0f) ? 1.0f : 0.0f;
            y2 = (v2 >= 1.0f) ? 1.0f : 0.0f;
            y3 = (v3 >= 1.0f) ? 1.0f : 0.0f;
            v0 = (y0 != 0.0f) ? 0.0f : v0;
            v1 = (y1 != 0.0f) ? 0.0f : v1;
            v2 = (y2 != 0.0f) ? 0.0f : v2;
            v3 = (y3 != 0.0f) ? 0.0f : v3;

            float4 o;
            o.x = y0; o.y = y1; o.z = y2; o.w = y3;
            out[(size_t)(tc + c) * S4 + idx] = o;
        }
    }
}

extern "C" void kernel_launch(void* const* d_in, const int* in_sizes, int n_in,
                              void* d_out, int out_size) {
    const float4* in = (const float4*)d_in[0];       // (T,N,C,J) f32
    const float4* w4 = (const float4*)d_in[1];       // (J,) f32
    float4* out = (float4*)d_out;                    // (T,N,C,J) f32

    const int threads = 128;
    const int blocks  = S4 / threads;                // 256
    spike_amplifier_kernel<<<blocks, threads>>>(in, w4, out);
}

// round 5
// speedup vs baseline: 1.1530x; 1.1530x over previous
#include <cuda_runtime.h>
#include <cuda_bf16.h>

// SpikeAmplifier: IF neuron with lateral amplification.
// input: (T=128, N=16, C=1, J=8192) f32 ; lateral_weight: (J=8192,) f32
// out:   (T, N, C, J) f32 spikes.
// Per neuron (n,j), sequential over t:
//   h = y_prev * (h + w[j]); v += x_t + h; s = (v >= 1); v = s ? 0 : v; emit s.
//
// Pure HBM-streaming recurrence. One scalar neuron per thread (131072 threads)
// for max warp-level latency hiding; double-buffered 16-deep prefetch keeps
// ~8MB in flight chip-wide; streaming cache hints (no reuse).

constexpr int T_STEPS = 128;
constexpr int J_DIM   = 8192;
constexpr int NCJ     = 16 * J_DIM;          // 131072 neurons
constexpr int CH      = 16;                  // prefetch depth (timesteps)

__global__ __launch_bounds__(128)
void spike_amplifier_kernel(const float* __restrict__ in,
                            const float* __restrict__ w,
                            float* __restrict__ out) {
    const int idx = blockIdx.x * blockDim.x + threadIdx.x;   // 0 .. NCJ-1
    const float wv = __ldg(w + (idx & (J_DIM - 1)));

    float h = 0.f, v = 0.f, y = 0.f;

    float buf[CH], nxt[CH];

    // Prime the pipeline: chunk 0 loads.
    #pragma unroll
    for (int c = 0; c < CH; c++)
        buf[c] = __ldcs(in + (size_t)c * NCJ + idx);

    #pragma unroll 1
    for (int tc = 0; tc < T_STEPS; tc += CH) {
        // Prefetch next chunk while this one computes (keeps DRAM busy).
        if (tc + CH < T_STEPS) {
            #pragma unroll
            for (int c = 0; c < CH; c++)
                nxt[c] = __ldcs(in + (size_t)(tc + CH + c) * NCJ + idx);
        }

        #pragma unroll
        for (int c = 0; c < CH; c++) {
            h = y * (h + wv);                 // lateral amplification
            v += buf[c] + h;                  // IF integration
            y = (v >= 1.0f) ? 1.0f : 0.0f;    // spike
            v = (y != 0.0f) ? 0.0f : v;       // hard reset
            __stcs(out + (size_t)(tc + c) * NCJ + idx, y);
        }

        #pragma unroll
        for (int c = 0; c < CH; c++)
            buf[c] = nxt[c];
    }
}

extern "C" void kernel_launch(void* const* d_in, const int* in_sizes, int n_in,
                              void* d_out, int out_size) {
    const float* in = (const float*)d_in[0];     // (T,N,C,J) f32
    const float* w  = (const float*)d_in[1];     // (J,) f32
    float* out = (float*)d_out;                  // (T,N,C,J) f32

    const int threads = 128;
    const int blocks  = NCJ / threads;           // 1024
    spike_amplifier_kernel<<<blocks, threads>>>(in, w, out);
}